// round 14
// baseline (speedup 1.0000x reference)
#include <cuda_runtime.h>
#include <cuda_fp16.h>
#include <cstdint>

#define NNODES 50000
#define NEDGES_MAX 800000
#define KDIM 128
#define NHID 128
#define NCLS 40
#define BN_EPS_F 1e-5f

#define SCAN_B 256
#define SCAN_NB ((NNODES + SCAN_B - 1) / SCAN_B)   // 196
#define EPT 8   // edges per thread in CSR-build kernels

#define GEMM_BX ((NNODES + 127) / 128)             // 391

// ---------------- scratch (device globals; zero-initialized at load) -------
// Invariant across calls/replays: g_degi == 0 at entry (gather2, the sole
// last reader of each entry, re-zeroes it at the end of every call).
__device__ int g_is64;
__device__ int g_degi[NNODES];
__device__ int g_rowptr[NNODES];
__device__ int g_cursor[NNODES];
__device__ int g_bsum[SCAN_NB];
__device__ int g_csrc[NEDGES_MAX];
__device__ __align__(16) __half2 g_Plh[(size_t)NNODES * (NHID / 2)]; // x @ W1l^T (fp16)
__device__ __align__(16) float g_Pr[(size_t)NNODES * NHID];          // x @ W1r^T
__device__ __align__(16) __half2 g_hh[(size_t)NNODES * (NHID / 2)];  // hidden (fp16)
__device__ __align__(16) __half2 g_Qlh[(size_t)NNODES * (NCLS / 2)]; // h @ W2l^T (fp16)
__device__ __align__(16) float g_Qr[(size_t)NNODES * NCLS];          // h @ W2r^T

__device__ __forceinline__ int edge_at(const void* eidx, int i) {
    if (g_is64) return (int)((const long long*)eidx)[i];
    return ((const int*)eidx)[i];
}

// ---------------- edge dtype detection (tiny kernel) ------------------------
__global__ void detect_kernel(const void* eidx) {
    if (threadIdx.x == 0) {
        const long long* q = (const long long*)eidx;
        int ok = 1;
        #pragma unroll
        for (int j = 0; j < 8; ++j) {
            long long v = q[j];
            if (v < 0 || v >= NNODES) ok = 0;
        }
        g_is64 = ok;
    }
}

// ---------------- degree histogram (8 edges/thread, batched loads) ----------
__global__ void deg_kernel(const void* __restrict__ eidx, int E) {
    int base = (blockIdx.x * blockDim.x + threadIdx.x) * EPT;
    int d[EPT];
    #pragma unroll
    for (int j = 0; j < EPT; ++j) {
        int e = base + j;
        d[j] = (e < E) ? edge_at(eidx, E + e) : -1;
    }
    #pragma unroll
    for (int j = 0; j < EPT; ++j)
        if (d[j] >= 0) atomicAdd(&g_degi[d[j]], 1);
}

// ---------------- scan phase A: per-block exclusive scan + block totals -----
__global__ __launch_bounds__(SCAN_B) void scanA_kernel() {
    __shared__ int s[SCAN_B];
    int tid = threadIdx.x;
    int i = blockIdx.x * SCAN_B + tid;
    int v = (i < NNODES) ? g_degi[i] : 0;
    s[tid] = v;
    __syncthreads();
    #pragma unroll
    for (int off = 1; off < SCAN_B; off <<= 1) {
        int t = (tid >= off) ? s[tid - off] : 0;
        __syncthreads();
        s[tid] += t;
        __syncthreads();
    }
    if (i < NNODES) g_rowptr[i] = s[tid] - v;
    if (tid == SCAN_B - 1) g_bsum[blockIdx.x] = s[tid];
}

// ---------------- scan phase BC (fused): per-block redundant offset ---------
__global__ __launch_bounds__(SCAN_B) void scanBC_kernel() {
    __shared__ int s[SCAN_B];
    int tid = threadIdx.x;
    int v = (tid < SCAN_NB && tid < blockIdx.x) ? g_bsum[tid] : 0;
    s[tid] = v;
    __syncthreads();
    #pragma unroll
    for (int off = SCAN_B / 2; off > 0; off >>= 1) {
        if (tid < off) s[tid] += s[tid + off];
        __syncthreads();
    }
    int off0 = s[0];
    int i = blockIdx.x * SCAN_B + tid;
    if (i < NNODES) {
        int r = g_rowptr[i] + off0;
        g_rowptr[i] = r;
        g_cursor[i] = r;
    }
}

// ---------------- CSR fill (8 edges/thread, batched loads) ------------------
__global__ void fill_kernel(const void* __restrict__ eidx, int E) {
    int base = (blockIdx.x * blockDim.x + threadIdx.x) * EPT;
    int s[EPT], d[EPT];
    #pragma unroll
    for (int j = 0; j < EPT; ++j) {
        int e = base + j;
        if (e < E) { s[j] = edge_at(eidx, e); d[j] = edge_at(eidx, E + e); }
        else       { s[j] = -1; d[j] = 0; }
    }
    #pragma unroll
    for (int j = 0; j < EPT; ++j) {
        if (s[j] >= 0) {
            int pos = atomicAdd(&g_cursor[d[j]], 1);
            g_csrc[pos] = s[j];
        }
    }
}

// ---------------- fp16 tensor-core GEMM (m16n8k16, fp32 accum) --------------
__device__ __forceinline__ uint32_t pack_h2(float a, float b) {
    __half2 h = __floats2half2_rn(a, b);
    return *(uint32_t*)&h;
}

__device__ __forceinline__ void mma_f16(float* c, const uint32_t* a,
                                        uint32_t b0, uint32_t b1) {
    asm volatile(
        "mma.sync.aligned.m16n8k16.row.col.f32.f16.f16.f32 "
        "{%0,%1,%2,%3}, {%4,%5,%6,%7}, {%8,%9}, {%0,%1,%2,%3};"
        : "+f"(c[0]), "+f"(c[1]), "+f"(c[2]), "+f"(c[3])
        : "r"(a[0]), "r"(a[1]), "r"(a[2]), "r"(a[3]), "r"(b0), "r"(b1));
}

// C = A[M,128] @ W[N,128]^T
// STAGE 1: A = Ax (f32),    by=0 -> g_Plh (fp16), by=1 -> g_Pr (f32)
// STAGE 2: A = g_hh (fp16), by=0 -> g_Qlh (fp16), by=1 -> g_Qr (f32)
template <int STAGE, int BM, int BN, int WARPS_M, int WARPS_N>
__global__ __launch_bounds__(WARPS_M * WARPS_N * 32) void gemm_tc(
    const float* __restrict__ Ax,
    const float* __restrict__ Wa, const float* __restrict__ Wb)
{
    constexpr int BK = 32;                 // k per smem tile
    constexpr int LDSU = BK / 2 + 4;       // 20 uint32 per row
    constexpr int WM = BM / WARPS_M;
    constexpr int WN = BN / WARPS_N;
    constexpr int MT = WM / 16;
    constexpr int NT = WN / 8;
    constexpr int THREADS = WARPS_M * WARPS_N * 32;

    __shared__ uint32_t As[BM][LDSU];
    __shared__ uint32_t Wsm[BN][LDSU];

    const float* W = blockIdx.y ? Wb : Wa;

    const int tid  = threadIdx.x;
    const int warp = tid >> 5;
    const int lane = tid & 31;
    const int gid  = lane >> 2;    // 0..7
    const int tq   = lane & 3;     // 0..3
    const int wm   = (warp % WARPS_M) * WM;
    const int wn   = (warp / WARPS_M) * WN;
    const int row0 = blockIdx.x * BM;

    float acc[MT][NT][4];
    #pragma unroll
    for (int i = 0; i < MT; ++i)
        #pragma unroll
        for (int j = 0; j < NT; ++j)
            #pragma unroll
            for (int r = 0; r < 4; ++r) acc[i][j][r] = 0.0f;

    for (int kt = 0; kt < KDIM; kt += BK) {
        // load A tile
        #pragma unroll
        for (int i = tid; i < BM * (BK / 4); i += THREADS) {
            int m = i / (BK / 4);
            int q = i % (BK / 4);          // 4 k-vals per chunk
            int row = row0 + m;
            if (STAGE == 1) {
                float4 v = make_float4(0.f, 0.f, 0.f, 0.f);
                if (row < NNODES)
                    v = *(const float4*)(Ax + (size_t)row * KDIM + kt + q * 4);
                As[m][q * 2 + 0] = pack_h2(v.x, v.y);
                As[m][q * 2 + 1] = pack_h2(v.z, v.w);
            } else {
                uint2 v = make_uint2(0u, 0u);
                if (row < NNODES)
                    v = *(const uint2*)((const uint32_t*)g_hh +
                                        (size_t)row * (KDIM / 2) + kt / 2 + q * 2);
                As[m][q * 2 + 0] = v.x;
                As[m][q * 2 + 1] = v.y;
            }
        }
        // load + convert W tile
        #pragma unroll
        for (int i = tid; i < BN * (BK / 4); i += THREADS) {
            int n = i / (BK / 4);
            int q = i % (BK / 4);
            float4 v = *(const float4*)(W + (size_t)n * KDIM + kt + q * 4);
            Wsm[n][q * 2 + 0] = pack_h2(v.x, v.y);
            Wsm[n][q * 2 + 1] = pack_h2(v.z, v.w);
        }
        __syncthreads();

        // 2 k-steps of 16 per BK=32 tile
        #pragma unroll
        for (int ks = 0; ks < BK / 16; ++ks) {
            int k0 = ks * 8;               // in half2 units
            uint32_t af[MT][4];
            #pragma unroll
            for (int mt = 0; mt < MT; ++mt) {
                int r = wm + mt * 16 + gid;
                af[mt][0] = As[r    ][k0 + tq];
                af[mt][1] = As[r + 8][k0 + tq];
                af[mt][2] = As[r    ][k0 + tq + 4];
                af[mt][3] = As[r + 8][k0 + tq + 4];
            }
            #pragma unroll
            for (int nt = 0; nt < NT; ++nt) {
                int n = wn + nt * 8 + gid;
                uint32_t b0 = Wsm[n][k0 + tq];
                uint32_t b1 = Wsm[n][k0 + tq + 4];
                #pragma unroll
                for (int mt = 0; mt < MT; ++mt)
                    mma_f16(acc[mt][nt], af[mt], b0, b1);
            }
        }
        __syncthreads();
    }

    const bool to_half = (blockIdx.y == 0);
    constexpr int LDC = (STAGE == 1) ? NHID : NCLS;
    float* Cf = (STAGE == 1) ? (float*)g_Pr : (float*)g_Qr;
    __half2* Ch = (STAGE == 1) ? g_Plh : g_Qlh;

    #pragma unroll
    for (int mt = 0; mt < MT; ++mt) {
        int r = row0 + wm + mt * 16 + gid;
        #pragma unroll
        for (int nt = 0; nt < NT; ++nt) {
            int c = wn + nt * 8 + 2 * tq;
            if (to_half) {
                if (r < NNODES)
                    Ch[(size_t)r * (LDC / 2) + c / 2] =
                        __floats2half2_rn(acc[mt][nt][0], acc[mt][nt][1]);
                if (r + 8 < NNODES)
                    Ch[(size_t)(r + 8) * (LDC / 2) + c / 2] =
                        __floats2half2_rn(acc[mt][nt][2], acc[mt][nt][3]);
            } else {
                if (r < NNODES)
                    *(float2*)(Cf + (size_t)r * LDC + c) =
                        make_float2(acc[mt][nt][0], acc[mt][nt][1]);
                if (r + 8 < NNODES)
                    *(float2*)(Cf + (size_t)(r + 8) * LDC + c) =
                        make_float2(acc[mt][nt][2], acc[mt][nt][3]);
            }
        }
    }
}

// ---------------- gather 1: h = BN(ReLU(inv*sum(Plh[nbr]) + Pr + b1)) -------
// h stored fp16 (gemm2 consumes fp16 anyway).
__global__ __launch_bounds__(256) void gather1_kernel(
    const float* __restrict__ b1, const float* __restrict__ gamma,
    const float* __restrict__ beta, const float* __restrict__ rmean,
    const float* __restrict__ rvar)
{
    int node = blockIdx.x * 8 + (threadIdx.x >> 5);
    if (node >= NNODES) return;
    int lane = threadIdx.x & 31;
    int start = g_rowptr[node];
    int deg   = g_degi[node];
    const __half2* Pl2 = g_Plh;

    float4 acc = make_float4(0.f, 0.f, 0.f, 0.f);
    int i = 0;
    for (; i + 8 <= deg; i += 8) {
        int sx[8];
        #pragma unroll
        for (int j = 0; j < 8; ++j) sx[j] = g_csrc[start + i + j];
        uint2 u[8];
        #pragma unroll
        for (int j = 0; j < 8; ++j)
            u[j] = *(const uint2*)(Pl2 + (size_t)sx[j] * 64 + lane * 2);
        #pragma unroll
        for (int j = 0; j < 8; ++j) {
            float2 a = __half22float2(*(const __half2*)&u[j].x);
            float2 b = __half22float2(*(const __half2*)&u[j].y);
            acc.x += a.x; acc.y += a.y; acc.z += b.x; acc.w += b.y;
        }
    }
    for (; i < deg; ++i) {
        int s = g_csrc[start + i];
        uint2 uu = *(const uint2*)(Pl2 + (size_t)s * 64 + lane * 2);
        float2 a = __half22float2(*(const __half2*)&uu.x);
        float2 b = __half22float2(*(const __half2*)&uu.y);
        acc.x += a.x; acc.y += a.y; acc.z += b.x; acc.w += b.y;
    }

    float inv = 1.0f / fmaxf((float)deg, 1.0f);
    float4 pr = ((const float4*)g_Pr)[(size_t)node * 32 + lane];
    int c = lane * 4;
    float av[4] = {acc.x * inv + pr.x, acc.y * inv + pr.y,
                   acc.z * inv + pr.z, acc.w * inv + pr.w};
    float hp[4];
    #pragma unroll
    for (int j = 0; j < 4; ++j) {
        int col = c + j;
        float val = fmaxf(av[j] + b1[col], 0.0f);
        float sc = gamma[col] * rsqrtf(rvar[col] + BN_EPS_F);
        hp[j] = val * sc + (beta[col] - rmean[col] * sc);
    }
    uint2 hv;
    hv.x = pack_h2(hp[0], hp[1]);
    hv.y = pack_h2(hp[2], hp[3]);
    *(uint2*)((uint32_t*)g_hh + (size_t)node * 64 + lane * 2) = hv;
}

// ---------------- gather 2: out = inv*sum(Qlh[nbr]) + Qr + b2 ---------------
// Restores the call-entry invariant: zeroes this node's degi entry.
__global__ __launch_bounds__(256) void gather2_kernel(
    const float* __restrict__ b2, float* __restrict__ out)
{
    int node = blockIdx.x * 8 + (threadIdx.x >> 5);
    if (node >= NNODES) return;
    int lane = threadIdx.x & 31;
    int cp = (lane < 20) ? lane : 0;   // inactive lanes alias col-pair 0
    int start = g_rowptr[node];
    int deg   = g_degi[node];
    if (lane == 0) g_degi[node] = 0;   // safe: this warp is the last reader

    float2 acc = make_float2(0.f, 0.f);
    int i = 0;
    for (; i + 8 <= deg; i += 8) {
        int sx[8];
        #pragma unroll
        for (int j = 0; j < 8; ++j) sx[j] = g_csrc[start + i + j];
        __half2 u[8];
        #pragma unroll
        for (int j = 0; j < 8; ++j)
            u[j] = g_Qlh[(size_t)sx[j] * 20 + cp];
        #pragma unroll
        for (int j = 0; j < 8; ++j) {
            float2 f = __half22float2(u[j]);
            acc.x += f.x; acc.y += f.y;
        }
    }
    for (; i < deg; ++i) {
        int s = g_csrc[start + i];
        float2 f = __half22float2(g_Qlh[(size_t)s * 20 + cp]);
        acc.x += f.x; acc.y += f.y;
    }

    if (lane < 20) {
        float inv = 1.0f / fmaxf((float)deg, 1.0f);
        float2 qr = *(const float2*)(g_Qr + (size_t)node * NCLS + 2 * lane);
        float2 bb = *(const float2*)(b2 + 2 * lane);
        *(float2*)(out + (size_t)node * NCLS + 2 * lane) =
            make_float2(acc.x * inv + qr.x + bb.x, acc.y * inv + qr.y + bb.y);
    }
}

// ---------------- launch (fork/join: CSR chain overlaps GEMM1) --------------
extern "C" void kernel_launch(void* const* d_in, const int* in_sizes, int n_in,
                              void* d_out, int out_size) {
    const float* x     = (const float*)d_in[0];
    const void*  ei    = d_in[1];
    const float* W1l   = (const float*)d_in[2];
    const float* b1    = (const float*)d_in[3];
    const float* W1r   = (const float*)d_in[4];
    const float* gamma = (const float*)d_in[5];
    const float* beta  = (const float*)d_in[6];
    const float* rmean = (const float*)d_in[7];
    const float* rvar  = (const float*)d_in[8];
    const float* W2l   = (const float*)d_in[9];
    const float* b2    = (const float*)d_in[10];
    const float* W2r   = (const float*)d_in[11];
    float* out = (float*)d_out;

    const int E = in_sizes[1] / 2;
    const int ebatch = (E + 256 * EPT - 1) / (256 * EPT);

    // side stream + fork/join events, created once on the first (uncaptured)
    // correctness call; reused (and recorded into the graph) on capture.
    static cudaStream_t s2 = nullptr;
    static cudaEvent_t evF = nullptr, evJ = nullptr;
    if (s2 == nullptr) {
        cudaStreamCreateWithFlags(&s2, cudaStreamNonBlocking);
        cudaEventCreateWithFlags(&evF, cudaEventDisableTiming);
        cudaEventCreateWithFlags(&evJ, cudaEventDisableTiming);
    }

    // fork: CSR chain on s2, GEMM1 on the main (capture) stream
    cudaEventRecord(evF, 0);
    cudaStreamWaitEvent(s2, evF, 0);

    detect_kernel<<<1, 32, 0, s2>>>(ei);
    deg_kernel<<<ebatch, 256, 0, s2>>>(ei, E);
    scanA_kernel<<<SCAN_NB, SCAN_B, 0, s2>>>();
    scanBC_kernel<<<SCAN_NB, SCAN_B, 0, s2>>>();
    fill_kernel<<<ebatch, 256, 0, s2>>>(ei, E);
    cudaEventRecord(evJ, s2);

    // P = x @ [W1l | W1r]^T   (fp16 tensor cores; Pl stored fp16)
    gemm_tc<1, 128, 128, 4, 2>
        <<<dim3(GEMM_BX, 2), 256>>>(x, W1l, W1r);

    // join: gather1 needs both GEMM1 (program order) and the CSR (event)
    cudaStreamWaitEvent(0, evJ, 0);

    // h = BN(ReLU(inv_deg * agg(Pl) + Pr + b1)), stored fp16
    gather1_kernel<<<(NNODES + 7) / 8, 256>>>(b1, gamma, beta, rmean, rvar);
    // Q = h @ [W2l | W2r]^T   (fp16 tensor cores; Ql stored fp16)
    gemm_tc<2, 128, 40, 8, 1>
        <<<dim3(GEMM_BX, 2), 256>>>(nullptr, W2l, W2r);
    // out = inv_deg * agg(Ql) + Qr + b2
    gather2_kernel<<<(NNODES + 7) / 8, 256>>>(b2, out);
}

// round 15
// speedup vs baseline: 1.5749x; 1.5749x over previous
#include <cuda_runtime.h>
#include <cuda_fp16.h>
#include <cstdint>

#define NNODES 50000
#define NEDGES_MAX 800000
#define KDIM 128
#define NHID 128
#define NCLS 40
#define BN_EPS_F 1e-5f

#define SCAN_B 256
#define SCAN_NB ((NNODES + SCAN_B - 1) / SCAN_B)   // 196
#define EPT 8   // edges per thread in CSR-build kernels

#define GEMM_BX ((NNODES + 127) / 128)             // 391

// ---------------- scratch (device globals; no runtime allocation) ----------
__device__ int g_is64;
__device__ int g_degi[NNODES];
__device__ int g_rowptr[NNODES];
__device__ int g_cursor[NNODES];
__device__ int g_bsum[SCAN_NB];
__device__ int g_csrc[NEDGES_MAX];
__device__ __align__(16) __half2 g_Plh[(size_t)NNODES * (NHID / 2)]; // x @ W1l^T (fp16)
__device__ __align__(16) float g_Pr[(size_t)NNODES * NHID];          // x @ W1r^T
__device__ __align__(16) __half2 g_hh[(size_t)NNODES * (NHID / 2)];  // hidden (fp16)
__device__ __align__(16) __half2 g_Qlh[(size_t)NNODES * (NCLS / 2)]; // h @ W2l^T (fp16)
__device__ __align__(16) float g_Qr[(size_t)NNODES * NCLS];          // h @ W2r^T

__device__ __forceinline__ int edge_at(const void* eidx, int i) {
    if (g_is64) return (int)((const long long*)eidx)[i];
    return ((const int*)eidx)[i];
}

// ---------------- zero degi + detect edge dtype (fused) ---------------------
__global__ void zero_detect_kernel(const void* eidx) {
    int i = blockIdx.x * blockDim.x + threadIdx.x;
    if (i < NNODES) g_degi[i] = 0;
    if (i == 0) {
        const long long* q = (const long long*)eidx;
        int ok = 1;
        #pragma unroll
        for (int j = 0; j < 8; ++j) {
            long long v = q[j];
            if (v < 0 || v >= NNODES) ok = 0;
        }
        g_is64 = ok;
    }
}

// ---------------- degree histogram (8 edges/thread, batched loads) ----------
__global__ void deg_kernel(const void* __restrict__ eidx, int E) {
    int base = (blockIdx.x * blockDim.x + threadIdx.x) * EPT;
    int d[EPT];
    #pragma unroll
    for (int j = 0; j < EPT; ++j) {
        int e = base + j;
        d[j] = (e < E) ? edge_at(eidx, E + e) : -1;
    }
    #pragma unroll
    for (int j = 0; j < EPT; ++j)
        if (d[j] >= 0) atomicAdd(&g_degi[d[j]], 1);
}

// ---------------- scan phase A: per-block exclusive scan + block totals -----
__global__ __launch_bounds__(SCAN_B) void scanA_kernel() {
    __shared__ int s[SCAN_B];
    int tid = threadIdx.x;
    int i = blockIdx.x * SCAN_B + tid;
    int v = (i < NNODES) ? g_degi[i] : 0;
    s[tid] = v;
    __syncthreads();
    #pragma unroll
    for (int off = 1; off < SCAN_B; off <<= 1) {
        int t = (tid >= off) ? s[tid - off] : 0;
        __syncthreads();
        s[tid] += t;
        __syncthreads();
    }
    if (i < NNODES) g_rowptr[i] = s[tid] - v;
    if (tid == SCAN_B - 1) g_bsum[blockIdx.x] = s[tid];
}

// ---------------- scan phase BC (fused): per-block redundant offset ---------
__global__ __launch_bounds__(SCAN_B) void scanBC_kernel() {
    __shared__ int s[SCAN_B];
    int tid = threadIdx.x;
    int v = (tid < SCAN_NB && tid < blockIdx.x) ? g_bsum[tid] : 0;
    s[tid] = v;
    __syncthreads();
    #pragma unroll
    for (int off = SCAN_B / 2; off > 0; off >>= 1) {
        if (tid < off) s[tid] += s[tid + off];
        __syncthreads();
    }
    int off0 = s[0];
    int i = blockIdx.x * SCAN_B + tid;
    if (i < NNODES) {
        int r = g_rowptr[i] + off0;
        g_rowptr[i] = r;
        g_cursor[i] = r;
    }
}

// ---------------- CSR fill (8 edges/thread, batched loads) ------------------
__global__ void fill_kernel(const void* __restrict__ eidx, int E) {
    int base = (blockIdx.x * blockDim.x + threadIdx.x) * EPT;
    int s[EPT], d[EPT];
    #pragma unroll
    for (int j = 0; j < EPT; ++j) {
        int e = base + j;
        if (e < E) { s[j] = edge_at(eidx, e); d[j] = edge_at(eidx, E + e); }
        else       { s[j] = -1; d[j] = 0; }
    }
    #pragma unroll
    for (int j = 0; j < EPT; ++j) {
        if (s[j] >= 0) {
            int pos = atomicAdd(&g_cursor[d[j]], 1);
            g_csrc[pos] = s[j];
        }
    }
}

// ---------------- fp16 tensor-core GEMM (m16n8k16, fp32 accum) --------------
__device__ __forceinline__ uint32_t pack_h2(float a, float b) {
    __half2 h = __floats2half2_rn(a, b);
    return *(uint32_t*)&h;
}

__device__ __forceinline__ void mma_f16(float* c, const uint32_t* a,
                                        uint32_t b0, uint32_t b1) {
    asm volatile(
        "mma.sync.aligned.m16n8k16.row.col.f32.f16.f16.f32 "
        "{%0,%1,%2,%3}, {%4,%5,%6,%7}, {%8,%9}, {%0,%1,%2,%3};"
        : "+f"(c[0]), "+f"(c[1]), "+f"(c[2]), "+f"(c[3])
        : "r"(a[0]), "r"(a[1]), "r"(a[2]), "r"(a[3]), "r"(b0), "r"(b1));
}

// C = A[M,128] @ W[N,128]^T
// STAGE 1: A = Ax (f32),    by=0 -> g_Plh (fp16), by=1 -> g_Pr (f32)
// STAGE 2: A = g_hh (fp16), by=0 -> g_Qlh (fp16), by=1 -> g_Qr (f32)
template <int STAGE, int BM, int BN, int WARPS_M, int WARPS_N>
__global__ __launch_bounds__(WARPS_M * WARPS_N * 32) void gemm_tc(
    const float* __restrict__ Ax,
    const float* __restrict__ Wa, const float* __restrict__ Wb)
{
    constexpr int BK = 32;                 // k per smem tile
    constexpr int LDSU = BK / 2 + 4;       // 20 uint32 per row
    constexpr int WM = BM / WARPS_M;
    constexpr int WN = BN / WARPS_N;
    constexpr int MT = WM / 16;
    constexpr int NT = WN / 8;
    constexpr int THREADS = WARPS_M * WARPS_N * 32;

    __shared__ uint32_t As[BM][LDSU];
    __shared__ uint32_t Wsm[BN][LDSU];

    const float* W = blockIdx.y ? Wb : Wa;

    const int tid  = threadIdx.x;
    const int warp = tid >> 5;
    const int lane = tid & 31;
    const int gid  = lane >> 2;    // 0..7
    const int tq   = lane & 3;     // 0..3
    const int wm   = (warp % WARPS_M) * WM;
    const int wn   = (warp / WARPS_M) * WN;
    const int row0 = blockIdx.x * BM;

    float acc[MT][NT][4];
    #pragma unroll
    for (int i = 0; i < MT; ++i)
        #pragma unroll
        for (int j = 0; j < NT; ++j)
            #pragma unroll
            for (int r = 0; r < 4; ++r) acc[i][j][r] = 0.0f;

    for (int kt = 0; kt < KDIM; kt += BK) {
        // load A tile
        #pragma unroll
        for (int i = tid; i < BM * (BK / 4); i += THREADS) {
            int m = i / (BK / 4);
            int q = i % (BK / 4);          // 4 k-vals per chunk
            int row = row0 + m;
            if (STAGE == 1) {
                float4 v = make_float4(0.f, 0.f, 0.f, 0.f);
                if (row < NNODES)
                    v = *(const float4*)(Ax + (size_t)row * KDIM + kt + q * 4);
                As[m][q * 2 + 0] = pack_h2(v.x, v.y);
                As[m][q * 2 + 1] = pack_h2(v.z, v.w);
            } else {
                uint2 v = make_uint2(0u, 0u);
                if (row < NNODES)
                    v = *(const uint2*)((const uint32_t*)g_hh +
                                        (size_t)row * (KDIM / 2) + kt / 2 + q * 2);
                As[m][q * 2 + 0] = v.x;
                As[m][q * 2 + 1] = v.y;
            }
        }
        // load + convert W tile
        #pragma unroll
        for (int i = tid; i < BN * (BK / 4); i += THREADS) {
            int n = i / (BK / 4);
            int q = i % (BK / 4);
            float4 v = *(const float4*)(W + (size_t)n * KDIM + kt + q * 4);
            Wsm[n][q * 2 + 0] = pack_h2(v.x, v.y);
            Wsm[n][q * 2 + 1] = pack_h2(v.z, v.w);
        }
        __syncthreads();

        // 2 k-steps of 16 per BK=32 tile
        #pragma unroll
        for (int ks = 0; ks < BK / 16; ++ks) {
            int k0 = ks * 8;               // in half2 units
            uint32_t af[MT][4];
            #pragma unroll
            for (int mt = 0; mt < MT; ++mt) {
                int r = wm + mt * 16 + gid;
                af[mt][0] = As[r    ][k0 + tq];
                af[mt][1] = As[r + 8][k0 + tq];
                af[mt][2] = As[r    ][k0 + tq + 4];
                af[mt][3] = As[r + 8][k0 + tq + 4];
            }
            #pragma unroll
            for (int nt = 0; nt < NT; ++nt) {
                int n = wn + nt * 8 + gid;
                uint32_t b0 = Wsm[n][k0 + tq];
                uint32_t b1 = Wsm[n][k0 + tq + 4];
                #pragma unroll
                for (int mt = 0; mt < MT; ++mt)
                    mma_f16(acc[mt][nt], af[mt], b0, b1);
            }
        }
        __syncthreads();
    }

    const bool to_half = (blockIdx.y == 0);
    constexpr int LDC = (STAGE == 1) ? NHID : NCLS;
    float* Cf = (STAGE == 1) ? (float*)g_Pr : (float*)g_Qr;
    __half2* Ch = (STAGE == 1) ? g_Plh : g_Qlh;

    #pragma unroll
    for (int mt = 0; mt < MT; ++mt) {
        int r = row0 + wm + mt * 16 + gid;
        #pragma unroll
        for (int nt = 0; nt < NT; ++nt) {
            int c = wn + nt * 8 + 2 * tq;
            if (to_half) {
                if (r < NNODES)
                    Ch[(size_t)r * (LDC / 2) + c / 2] =
                        __floats2half2_rn(acc[mt][nt][0], acc[mt][nt][1]);
                if (r + 8 < NNODES)
                    Ch[(size_t)(r + 8) * (LDC / 2) + c / 2] =
                        __floats2half2_rn(acc[mt][nt][2], acc[mt][nt][3]);
            } else {
                if (r < NNODES)
                    *(float2*)(Cf + (size_t)r * LDC + c) =
                        make_float2(acc[mt][nt][0], acc[mt][nt][1]);
                if (r + 8 < NNODES)
                    *(float2*)(Cf + (size_t)(r + 8) * LDC + c) =
                        make_float2(acc[mt][nt][2], acc[mt][nt][3]);
            }
        }
    }
}

// ---------------- gather 1: h = BN(ReLU(inv*sum(Plh[nbr]) + Pr + b1)) -------
// h stored fp16 (gemm2 consumes fp16 anyway).
__global__ __launch_bounds__(256) void gather1_kernel(
    const float* __restrict__ b1, const float* __restrict__ gamma,
    const float* __restrict__ beta, const float* __restrict__ rmean,
    const float* __restrict__ rvar)
{
    int node = blockIdx.x * 8 + (threadIdx.x >> 5);
    if (node >= NNODES) return;
    int lane = threadIdx.x & 31;
    int start = g_rowptr[node];
    int deg   = g_degi[node];
    const __half2* Pl2 = g_Plh;

    float4 acc = make_float4(0.f, 0.f, 0.f, 0.f);
    int i = 0;
    for (; i + 8 <= deg; i += 8) {
        int sx[8];
        #pragma unroll
        for (int j = 0; j < 8; ++j) sx[j] = g_csrc[start + i + j];
        uint2 u[8];
        #pragma unroll
        for (int j = 0; j < 8; ++j)
            u[j] = *(const uint2*)(Pl2 + (size_t)sx[j] * 64 + lane * 2);
        #pragma unroll
        for (int j = 0; j < 8; ++j) {
            float2 a = __half22float2(*(const __half2*)&u[j].x);
            float2 b = __half22float2(*(const __half2*)&u[j].y);
            acc.x += a.x; acc.y += a.y; acc.z += b.x; acc.w += b.y;
        }
    }
    for (; i < deg; ++i) {
        int s = g_csrc[start + i];
        uint2 uu = *(const uint2*)(Pl2 + (size_t)s * 64 + lane * 2);
        float2 a = __half22float2(*(const __half2*)&uu.x);
        float2 b = __half22float2(*(const __half2*)&uu.y);
        acc.x += a.x; acc.y += a.y; acc.z += b.x; acc.w += b.y;
    }

    float inv = 1.0f / fmaxf((float)deg, 1.0f);
    float4 pr = ((const float4*)g_Pr)[(size_t)node * 32 + lane];
    int c = lane * 4;
    float av[4] = {acc.x * inv + pr.x, acc.y * inv + pr.y,
                   acc.z * inv + pr.z, acc.w * inv + pr.w};
    float hp[4];
    #pragma unroll
    for (int j = 0; j < 4; ++j) {
        int col = c + j;
        float val = fmaxf(av[j] + b1[col], 0.0f);
        float sc = gamma[col] * rsqrtf(rvar[col] + BN_EPS_F);
        hp[j] = val * sc + (beta[col] - rmean[col] * sc);
    }
    uint2 hv;
    hv.x = pack_h2(hp[0], hp[1]);
    hv.y = pack_h2(hp[2], hp[3]);
    *(uint2*)((uint32_t*)g_hh + (size_t)node * 64 + lane * 2) = hv;
}

// ---------------- gather 2: out = inv*sum(Qlh[nbr]) + Qr + b2 ---------------
__global__ __launch_bounds__(256) void gather2_kernel(
    const float* __restrict__ b2, float* __restrict__ out)
{
    int node = blockIdx.x * 8 + (threadIdx.x >> 5);
    if (node >= NNODES) return;
    int lane = threadIdx.x & 31;
    int cp = (lane < 20) ? lane : 0;   // inactive lanes alias col-pair 0
    int start = g_rowptr[node];
    int deg   = g_degi[node];

    float2 acc = make_float2(0.f, 0.f);
    int i = 0;
    for (; i + 8 <= deg; i += 8) {
        int sx[8];
        #pragma unroll
        for (int j = 0; j < 8; ++j) sx[j] = g_csrc[start + i + j];
        __half2 u[8];
        #pragma unroll
        for (int j = 0; j < 8; ++j)
            u[j] = g_Qlh[(size_t)sx[j] * 20 + cp];
        #pragma unroll
        for (int j = 0; j < 8; ++j) {
            float2 f = __half22float2(u[j]);
            acc.x += f.x; acc.y += f.y;
        }
    }
    for (; i < deg; ++i) {
        int s = g_csrc[start + i];
        float2 f = __half22float2(g_Qlh[(size_t)s * 20 + cp]);
        acc.x += f.x; acc.y += f.y;
    }

    if (lane < 20) {
        float inv = 1.0f / fmaxf((float)deg, 1.0f);
        float2 qr = *(const float2*)(g_Qr + (size_t)node * NCLS + 2 * lane);
        float2 bb = *(const float2*)(b2 + 2 * lane);
        *(float2*)(out + (size_t)node * NCLS + 2 * lane) =
            make_float2(acc.x * inv + qr.x + bb.x, acc.y * inv + qr.y + bb.y);
    }
}

// ---------------- launch (fork/join: CSR chain overlaps GEMM1) --------------
extern "C" void kernel_launch(void* const* d_in, const int* in_sizes, int n_in,
                              void* d_out, int out_size) {
    const float* x     = (const float*)d_in[0];
    const void*  ei    = d_in[1];
    const float* W1l   = (const float*)d_in[2];
    const float* b1    = (const float*)d_in[3];
    const float* W1r   = (const float*)d_in[4];
    const float* gamma = (const float*)d_in[5];
    const float* beta  = (const float*)d_in[6];
    const float* rmean = (const float*)d_in[7];
    const float* rvar  = (const float*)d_in[8];
    const float* W2l   = (const float*)d_in[9];
    const float* b2    = (const float*)d_in[10];
    const float* W2r   = (const float*)d_in[11];
    float* out = (float*)d_out;

    const int E = in_sizes[1] / 2;
    const int ebatch = (E + 256 * EPT - 1) / (256 * EPT);

    // side stream + fork/join events, created once on the first (uncaptured)
    // correctness call; reused (and recorded into the graph) on capture.
    static cudaStream_t s2 = nullptr;
    static cudaEvent_t evF = nullptr, evJ = nullptr;
    if (s2 == nullptr) {
        cudaStreamCreateWithFlags(&s2, cudaStreamNonBlocking);
        cudaEventCreateWithFlags(&evF, cudaEventDisableTiming);
        cudaEventCreateWithFlags(&evJ, cudaEventDisableTiming);
    }

    // fork: CSR chain on s2, GEMM1 on the main (capture) stream
    cudaEventRecord(evF, 0);
    cudaStreamWaitEvent(s2, evF, 0);

    zero_detect_kernel<<<(NNODES + 255) / 256, 256, 0, s2>>>(ei);
    deg_kernel<<<ebatch, 256, 0, s2>>>(ei, E);
    scanA_kernel<<<SCAN_NB, SCAN_B, 0, s2>>>();
    scanBC_kernel<<<SCAN_NB, SCAN_B, 0, s2>>>();
    fill_kernel<<<ebatch, 256, 0, s2>>>(ei, E);
    cudaEventRecord(evJ, s2);

    // P = x @ [W1l | W1r]^T   (fp16 tensor cores; Pl stored fp16)
    gemm_tc<1, 128, 128, 4, 2>
        <<<dim3(GEMM_BX, 2), 256>>>(x, W1l, W1r);

    // join: gather1 needs both GEMM1 (program order) and the CSR (event)
    cudaStreamWaitEvent(0, evJ, 0);

    // h = BN(ReLU(inv_deg * agg(Pl) + Pr + b1)), stored fp16
    gather1_kernel<<<(NNODES + 7) / 8, 256>>>(b1, gamma, beta, rmean, rvar);
    // Q = h @ [W2l | W2r]^T   (fp16 tensor cores; Ql stored fp16)
    gemm_tc<2, 128, 40, 8, 1>
        <<<dim3(GEMM_BX, 2), 256>>>(nullptr, W2l, W2r);
    // out = inv_deg * agg(Ql) + Qr + b2
    gather2_kernel<<<(NNODES + 7) / 8, 256>>>(b2, out);
}